// round 8
// baseline (speedup 1.0000x reference)
#include <cuda_runtime.h>
#include <cuda_bf16.h>
#include <math.h>

// Problem constants
#define BB   16
#define PP   4096
#define MM   1024
#define KK   16
#define FIN  64
#define FOUT 128
#define NN   (BB * PP)          // 65536
#define BN_EPS 1e-5f

#define OFF_P  (BB * MM * FOUT)            // 2097152
#define OFF_B  (OFF_P + BB * MM * 3)       // 2146304
#define TOTAL_OUT (OFF_B + BB * MM)        // 2162688

// f32x2 packed ops (sm_103a). fma.rn.f32x2 / add.rn.f32x2 / mul.rn.f32x2 are
// two independent rn-rounded fp32 ops -> bitwise identical to scalar code.
#define PACK2(o, lo, hi)  asm("mov.b64 %0, {%1, %2};" : "=l"(o) : "f"(lo), "f"(hi))
#define UNPACK2(lo, hi, i) asm("mov.b64 {%0, %1}, %2;" : "=f"(lo), "=f"(hi) : "l"(i))
#define FMA2(acc, a, b)   asm("fma.rn.f32x2 %0, %1, %2, %0;" : "+l"(acc) : "l"(a), "l"(b))
#define ADD2(o, a, b)     asm("add.rn.f32x2 %0, %1, %2;" : "=l"(o) : "l"(a), "l"(b))
#define MUL2(o, a, b)     asm("mul.rn.f32x2 %0, %1, %2;" : "=l"(o) : "l"(a), "l"(b))

typedef unsigned long long ull;

// -------- scratch (static device globals; no allocation allowed) --------
__device__ int   g_fps[BB * MM];
__device__ int   g_knn[BB * MM * KK];
__device__ float g_h[(size_t)NN * FOUT];        // 33.5 MB pre-BN activations
__device__ float g_psum[(NN / 32) * FOUT];      // 2048 x 128 partial sums
__device__ float g_psq [(NN / 32) * FOUT];
__device__ float g_mean[FOUT];
__device__ float g_var [FOUT];
__device__ float g_xx[NN];                      // per-point sum(x*x) in feature space

// ============================================================
// Fused kernel: blocks 0..15 run FPS (one cloud each, 1024 thr),
// blocks 16..271 run the MLP (+xx) on 256 rows each (1024 thr).
// ============================================================
__global__ void __launch_bounds__(1024) fused_fps_mlp_kernel(
    const float* __restrict__ pos,
    const float* __restrict__ feat,
    const float* __restrict__ W,
    const float* __restrict__ bias)
{
    extern __shared__ float fsm[];
    const int tid = threadIdx.x;

    if (blockIdx.x < BB) {
        // ---------------- FPS path ----------------
        float* sx = fsm;
        float* sy = fsm + PP;
        float* sz = fsm + 2 * PP;
        uint2* swp = (uint2*)(fsm + 3 * PP);   // double-buffered: 2 x 32

        const int b    = blockIdx.x;
        const int lane = tid & 31;
        const int wid  = tid >> 5;

        const float* pb = pos + (size_t)b * PP * 3;
        for (int j = tid; j < PP; j += 1024) {
            sx[j] = pb[3 * j + 0];
            sy[j] = pb[3 * j + 1];
            sz[j] = pb[3 * j + 2];
        }
        __syncthreads();

        float x0 = sx[tid],        x1 = sx[tid + 1024], x2 = sx[tid + 2048], x3 = sx[tid + 3072];
        float y0 = sy[tid],        y1 = sy[tid + 1024], y2 = sy[tid + 2048], y3 = sy[tid + 3072];
        float z0 = sz[tid],        z1 = sz[tid + 1024], z2 = sz[tid + 2048], z3 = sz[tid + 3072];
        ull X01, X23, Y01, Y23, Z01, Z23;
        PACK2(X01, x0, x1); PACK2(X23, x2, x3);
        PACK2(Y01, y0, y1); PACK2(Y23, y2, y3);
        PACK2(Z01, z0, z1); PACK2(Z23, z2, z3);
        float dist0 = INFINITY, dist1 = INFINITY, dist2 = INFINITY, dist3 = INFINITY;

        if (tid == 0) g_fps[b * MM] = 0;

        int last = 0;
        for (int i = 1; i < MM; i++) {
            float lx = sx[last], ly = sy[last], lz = sz[last];
            float nlx = -lx, nly = -ly, nlz = -lz;
            ull NLX, NLY, NLZ;
            PACK2(NLX, nlx, nlx); PACK2(NLY, nly, nly); PACK2(NLZ, nlz, nlz);

            // d = ((dx*dx + dy*dy) + dz*dz), no fma -> bitwise == scalar rn
            ull dx, dy, dz, mx, my, mz, t, d01, d23;
            ADD2(dx, X01, NLX); ADD2(dy, Y01, NLY); ADD2(dz, Z01, NLZ);
            MUL2(mx, dx, dx); MUL2(my, dy, dy); MUL2(mz, dz, dz);
            ADD2(t, mx, my); ADD2(d01, t, mz);
            ADD2(dx, X23, NLX); ADD2(dy, Y23, NLY); ADD2(dz, Z23, NLZ);
            MUL2(mx, dx, dx); MUL2(my, dy, dy); MUL2(mz, dz, dz);
            ADD2(t, mx, my); ADD2(d23, t, mz);

            float d0, d1, d2f, d3f;
            UNPACK2(d0, d1, d01); UNPACK2(d2f, d3f, d23);

            dist0 = fminf(dist0, d0);
            dist1 = fminf(dist1, d1);
            dist2 = fminf(dist2, d2f);
            dist3 = fminf(dist3, d3f);

            // per-thread argmax (ascending slot index, strict > keeps min index)
            float bv = -1.0f; unsigned bj = 0;
            if (dist0 > bv) { bv = dist0; bj = (unsigned)tid; }
            if (dist1 > bv) { bv = dist1; bj = (unsigned)(tid + 1024); }
            if (dist2 > bv) { bv = dist2; bj = (unsigned)(tid + 2048); }
            if (dist3 > bv) { bv = dist3; bj = (unsigned)(tid + 3072); }

            // warp argmax with first-index tie-break (dist >= 0 -> bits order-preserving)
            unsigned vb = __float_as_uint(bv);
            unsigned wm = __reduce_max_sync(0xffffffffu, vb);
            unsigned cj = (vb == wm) ? bj : 0xffffffffu;
            unsigned wj = __reduce_min_sync(0xffffffffu, cj);

            uint2* buf = swp + ((i & 1) << 5);
            if (lane == 0) buf[wid] = make_uint2(wm, wj);
            __syncthreads();
            // all warps redundantly reduce the 32 warp results (single barrier/iter:
            // next iter writes the OTHER buffer; barrier of iter i+1 protects reuse)
            uint2 e = buf[lane];
            unsigned gm  = __reduce_max_sync(0xffffffffu, e.x);
            unsigned cj2 = (e.x == gm) ? e.y : 0xffffffffu;
            unsigned gj  = __reduce_min_sync(0xffffffffu, cj2);
            last = (int)gj;
            if (tid == 0) g_fps[b * MM + i] = last;
        }
    } else {
        // ---------------- MLP (+xx) path: 256 rows per block ----------------
        float* sW = fsm;               // 64*128 = 8192 floats (32 KB)
        float* sF = fsm + FIN * FOUT;  // 256*64 = 16384 floats (64 KB)

        const int row0 = (blockIdx.x - BB) * 256;

        for (int l = tid; l < FIN * FOUT; l += 1024) sW[l] = W[l];
        float4* sF4 = (float4*)sF;
        const float4* feat4 = (const float4*)(feat + (size_t)row0 * FIN);
        for (int l = tid; l < 256 * (FIN / 4); l += 1024) sF4[l] = feat4[l];
        __syncthreads();

        if (tid < 256) {
            float a0 = 0.f, a1 = 0.f, a2 = 0.f, a3 = 0.f;
#pragma unroll
            for (int d = 0; d < FIN / 4; d++) {
                float4 v = sF4[tid * (FIN / 4) + d];
                a0 += v.x * v.x; a1 += v.y * v.y; a2 += v.z * v.z; a3 += v.w * v.w;
            }
            g_xx[row0 + tid] = (a0 + a1) + (a2 + a3);
        }

        const int col = tid & 127;
        const int grp = tid >> 7;          // 0..7, 32 rows each
        const int rbase = grp * 32;
        const float bc = bias[col];
        float s1 = 0.f, s2 = 0.f;

        for (int r = rbase; r < rbase + 32; r += 2) {
            float a0 = bc, a1 = bc;
#pragma unroll
            for (int d4 = 0; d4 < FIN / 4; d4++) {
                float4 f0 = sF4[r * (FIN / 4) + d4];
                float4 f1 = sF4[(r + 1) * (FIN / 4) + d4];
                float w0 = sW[(d4 * 4 + 0) * FOUT + col];
                float w1 = sW[(d4 * 4 + 1) * FOUT + col];
                float w2 = sW[(d4 * 4 + 2) * FOUT + col];
                float w3 = sW[(d4 * 4 + 3) * FOUT + col];
                a0 += f0.x * w0; a0 += f0.y * w1; a0 += f0.z * w2; a0 += f0.w * w3;
                a1 += f1.x * w0; a1 += f1.y * w1; a1 += f1.z * w2; a1 += f1.w * w3;
            }
            g_h[(size_t)(row0 + r)     * FOUT + col] = a0;
            g_h[(size_t)(row0 + r + 1) * FOUT + col] = a1;
            s1 += a0 + a1;
            s2 += a0 * a0 + a1 * a1;
        }
        const int prow = row0 / 32 + grp;   // 0..2047
        g_psum[prow * FOUT + col] = s1;
        g_psq [prow * FOUT + col] = s2;
    }
}

// Deterministic BN stat reduction: one block per column, fixed-order tree.
__global__ void bn_reduce_kernel()
{
    __shared__ float r1[256], r2[256];
    const int col = blockIdx.x;
    const int tid = threadIdx.x;
    float s1 = 0.f, s2 = 0.f;
    for (int i = tid; i < (NN / 32); i += 256) {
        s1 += g_psum[i * FOUT + col];
        s2 += g_psq [i * FOUT + col];
    }
    r1[tid] = s1; r2[tid] = s2;
    __syncthreads();
    for (int off = 128; off > 0; off >>= 1) {
        if (tid < off) { r1[tid] += r1[tid + off]; r2[tid] += r2[tid + off]; }
        __syncthreads();
    }
    if (tid == 0) {
        float mean = r1[0] / (float)NN;
        float var  = r2[0] / (float)NN - mean * mean;
        if (var < 0.f) var = 0.f;
        g_mean[col] = mean;
        g_var [col] = var;
    }
}

// ============================================================
// KNN v2: 128 blocks x 256 threads. Block = 128 queries of one
// cloud chunk; 2 candidate-subsets of 2048 each (sub = tid>>7).
// 256 regs/thread budget -> no spills. Same exact arithmetic
// (fma.rn.f32x2 = the FFMA-contracted 4-accumulator chains).
// Merge: per-thread register sort of 16 (d2,idx) keys, then exact
// 2-pointer merge of the two sorted lists.
// ============================================================
__global__ void __launch_bounds__(256) knn_kernel(const float* __restrict__ feat)
{
    extern __shared__ char ksm[];
    float* sTile = (float*)ksm;                 // 2*32*64 f32 = 16 KB (loop phase)
    ull*   mbuf  = (ull*)ksm;                   // 32*128*8B  = 32 KB (merge phase)
    float* sxx   = (float*)(ksm + 32768);       // 64 f32

    const int tid = threadIdx.x;
    const int sub = tid >> 7;          // 0..1  (candidate half)
    const int q   = tid & 127;
    const int b     = blockIdx.x >> 3;
    const int chunk = blockIdx.x & 7;
    const int m = chunk * 128 + q;

    const int qi = g_fps[b * MM + m];
    const float4* qrow = (const float4*)(feat + ((size_t)b * PP + qi) * FIN);
    ull qp[32];
#pragma unroll
    for (int d = 0; d < FIN / 4; d++) {
        float4 f = qrow[d];
        PACK2(qp[2 * d],     f.x, f.y);
        PACK2(qp[2 * d + 1], f.z, f.w);
    }
    const float qq = g_xx[(size_t)b * PP + qi];

    float topv[KK];
    int   topi[KK];
#pragma unroll
    for (int s = 0; s < KK; s++) { topv[s] = INFINITY; topi[s] = 0x7fffffff; }
    float worst = INFINITY;

    const float4* fb4 = (const float4*)(feat + (size_t)b * PP * FIN);
    float4* sT4 = (float4*)sTile;

    for (int p0 = 0; p0 < 2048; p0 += 32) {
        __syncthreads();
        // tile load: 64 rows (32 per sub) x 16 float4 = 1024 float4, 4/thread
#pragma unroll
        for (int i = 0; i < 4; i++) {
            int l   = i * 256 + tid;    // 0..1023
            int row = l >> 4;           // 0..63 : sub = row>>5, c = row&31
            int c4  = l & 15;
            int grow = (row >> 5) * 2048 + p0 + (row & 31);
            sT4[l] = fb4[(size_t)grow * (FIN / 4) + c4];
        }
        if (tid < 64)
            sxx[tid] = g_xx[(size_t)b * PP + (tid >> 5) * 2048 + p0 + (tid & 31)];
        __syncthreads();

#pragma unroll 2
        for (int c = 0; c < 32; c++) {
            const ulonglong2* xr = (const ulonglong2*)(sTile + (size_t)(sub * 32 + c) * FIN);
            ull a01 = 0ull, a23 = 0ull;
#pragma unroll
            for (int d = 0; d < FIN / 4; d++) {
                ulonglong2 xv = xr[d];
                FMA2(a01, qp[2 * d],     xv.x);
                FMA2(a23, qp[2 * d + 1], xv.y);
            }
            float a0, a1, a2, a3;
            UNPACK2(a0, a1, a01);
            UNPACK2(a2, a3, a23);
            float dot = (a0 + a1) + (a2 + a3);
            float d2  = (qq - 2.0f * dot) + sxx[sub * 32 + c];
            if (d2 < worst) {
                int cand = sub * 2048 + p0 + c;
                float mv = topv[0]; int mi = topi[0]; int msl = 0;
#pragma unroll
                for (int s = 1; s < KK; s++) {
                    bool better = (topv[s] > mv) || (topv[s] == mv && topi[s] > mi);
                    if (better) { mv = topv[s]; mi = topi[s]; msl = s; }
                }
#pragma unroll
                for (int s = 0; s < KK; s++) {
                    if (s == msl) { topv[s] = d2; topi[s] = cand; }
                }
                worst = topv[0];
#pragma unroll
                for (int s = 1; s < KK; s++) worst = fmaxf(worst, topv[s]);
            }
        }
    }

    // ---- per-thread: pack (monotone(d2)<<32 | idx) keys and sort ascending ----
    ull key[KK];
#pragma unroll
    for (int s = 0; s < KK; s++) {
        unsigned v = __float_as_uint(topv[s]);
        unsigned u = (v & 0x80000000u) ? ~v : (v | 0x80000000u);
        key[s] = ((ull)u << 32) | (unsigned)topi[s];
    }
#pragma unroll
    for (int i = 0; i < KK - 1; i++) {
#pragma unroll
        for (int j = i + 1; j < KK; j++) {
            if (key[j] < key[i]) { ull t = key[i]; key[i] = key[j]; key[j] = t; }
        }
    }

    __syncthreads();   // tile reads done; reuse smem as mbuf
#pragma unroll
    for (int s = 0; s < KK; s++)
        mbuf[(size_t)(sub * KK + s) * 128 + q] = key[s];
    __syncthreads();

    // ---- exact 2-pointer merge of the two sorted lists ----
    if (sub == 0) {
        int base = (b * MM + m) * KK;
        ull c0 = mbuf[(size_t)0 * 128 + q];
        ull c1 = mbuf[(size_t)KK * 128 + q];
        int h0 = 0, h1 = 0;
#pragma unroll
        for (int k = 0; k < KK; k++) {
            bool take0 = (c0 < c1);
            ull w = take0 ? c0 : c1;
            g_knn[base + k] = (int)(unsigned)(w & 0xffffffffu);
            if (take0) {
                h0++;
                c0 = (h0 < KK) ? mbuf[(size_t)h0 * 128 + q] : 0xffffffffffffffffull;
            } else {
                h1++;
                c1 = (h1 < KK) ? mbuf[(size_t)(KK + h1) * 128 + q] : 0xffffffffffffffffull;
            }
        }
    }
}

// ============================================================
// Gather + fused BN + ReLU + max-pool over K neighbors.
// ============================================================
__global__ void gather_kernel(const float* __restrict__ pos,
                              const float* __restrict__ gamma,
                              const float* __restrict__ beta,
                              float* __restrict__ out,
                              int out_size)
{
    __shared__ int sidx[KK];
    __shared__ int sfps;
    const int q   = blockIdx.x;
    const int b   = q >> 10;
    const int tid = threadIdx.x;

    if (tid < KK) sidx[tid] = g_knn[q * KK + tid];
    if (tid == KK) sfps = g_fps[q];
    __syncthreads();

    const int col = tid;
    float mean = g_mean[col];
    float rstd = rsqrtf(g_var[col] + BN_EPS);
    float ga = gamma[col], be = beta[col];
    const float* hb = g_h + (size_t)b * PP * FOUT;

    float mx = -INFINITY;
#pragma unroll
    for (int k = 0; k < KK; k++) {
        float v = hb[(size_t)sidx[k] * FOUT + col];
        v = (v - mean) * rstd * ga + be;
        v = fmaxf(v, 0.f);
        mx = fmaxf(mx, v);
    }
    out[(size_t)q * FOUT + col] = mx;

    if (out_size >= TOTAL_OUT) {
        if (tid < 3) out[OFF_P + q * 3 + tid] = pos[((size_t)b * PP + sfps) * 3 + tid];
        if (tid == 3) out[OFF_B + q] = (float)b;
    }
}

// ============================================================
extern "C" void kernel_launch(void* const* d_in, const int* in_sizes, int n_in,
                              void* d_out, int out_size)
{
    const float* pos   = (const float*)d_in[0];
    const float* feat  = (const float*)d_in[1];
    // d_in[2] = batch_indices (unused: clouds are sorted & equal-sized)
    const float* W     = (const float*)d_in[3];
    const float* bias  = (const float*)d_in[4];
    const float* gamma = (const float*)d_in[5];
    const float* beta  = (const float*)d_in[6];
    float* out = (float*)d_out;

    const int fused_smem = (FIN * FOUT + 256 * FIN) * sizeof(float);   // 98304
    cudaFuncSetAttribute(fused_fps_mlp_kernel, cudaFuncAttributeMaxDynamicSharedMemorySize, fused_smem);
    const int knn_smem = 32768 + 64 * sizeof(float);                   // 33024
    cudaFuncSetAttribute(knn_kernel, cudaFuncAttributeMaxDynamicSharedMemorySize, knn_smem);

    // FPS (16 blocks) runs concurrently with MLP+xx (256 blocks).
    fused_fps_mlp_kernel<<<BB + 256, 1024, fused_smem>>>(pos, feat, W, bias);
    knn_kernel<<<BB * (MM / 128), 256, knn_smem>>>(feat);
    bn_reduce_kernel<<<FOUT, 256>>>();
    gather_kernel<<<BB * MM, 128>>>(pos, gamma, beta, out, out_size);
}

// round 9
// speedup vs baseline: 1.3590x; 1.3590x over previous
#include <cuda_runtime.h>
#include <cuda_bf16.h>
#include <math.h>

// Problem constants
#define BB   16
#define PP   4096
#define MM   1024
#define KK   16
#define FIN  64
#define FOUT 128
#define NN   (BB * PP)          // 65536
#define BN_EPS 1e-5f

#define OFF_P  (BB * MM * FOUT)            // 2097152
#define OFF_B  (OFF_P + BB * MM * 3)       // 2146304
#define TOTAL_OUT (OFF_B + BB * MM)        // 2162688

#define N_MLP_BLOCKS 256
#define N_KNN_BLOCKS 128
#define MEGA_BLOCKS  (BB + N_MLP_BLOCKS + N_KNN_BLOCKS)   // 400

// f32x2 packed ops (sm_103a): two independent rn-rounded fp32 ops ->
// bitwise identical to the scalar sequences they replace.
#define PACK2(o, lo, hi)  asm("mov.b64 %0, {%1, %2};" : "=l"(o) : "f"(lo), "f"(hi))
#define UNPACK2(lo, hi, i) asm("mov.b64 {%0, %1}, %2;" : "=f"(lo), "=f"(hi) : "l"(i))
#define FMA2(acc, a, b)   asm("fma.rn.f32x2 %0, %1, %2, %0;" : "+l"(acc) : "l"(a), "l"(b))
#define ADD2(o, a, b)     asm("add.rn.f32x2 %0, %1, %2;" : "=l"(o) : "l"(a), "l"(b))
#define MUL2(o, a, b)     asm("mul.rn.f32x2 %0, %1, %2;" : "=l"(o) : "l"(a), "l"(b))

typedef unsigned long long ull;

// -------- scratch (static device globals; no allocation allowed) --------
__device__ int   g_fps[BB * MM];
__device__ int   g_knn[BB * MM * KK];
__device__ float g_h[(size_t)NN * FOUT];        // 33.5 MB pre-BN activations
__device__ float g_psum[1024 * FOUT];           // 1024 x 128 partial sums (64 rows each)
__device__ float g_psq [1024 * FOUT];
__device__ float g_mean[FOUT];
__device__ float g_var [FOUT];
__device__ float g_xx[NN];                      // per-point sum(x*x) in feature space
// cross-block progress (reset by init kernel every call)
__device__ int   g_prog[BB];                    // fps indices published per cloud
__device__ int   g_mlp_done;                    // completed mlp blocks

__global__ void init_kernel()
{
    int t = threadIdx.x;
    if (t < BB) g_prog[t] = 0;
    if (t == 31) g_mlp_done = 0;
}

// ============================================================
// Mega kernel, 512 threads/block:
//   blocks [0,16)          : FPS (one cloud each, publishes progress/128)
//   blocks [16,272)        : MLP (+xx) on 256 rows each, signals done
//   blocks [272,400)       : KNN chunk (128 queries), spins on progress,
//                            then runs the R3-passing KNN body verbatim.
// ============================================================
__global__ void __launch_bounds__(512) mega_kernel(
    const float* __restrict__ pos,
    const float* __restrict__ feat,
    const float* __restrict__ W,
    const float* __restrict__ bias)
{
    extern __shared__ float fsm[];
    const int tid = threadIdx.x;
    const int bid = blockIdx.x;

    if (bid < BB) {
        // ---------------- FPS path: 512 thr, 8 pts/thread ----------------
        float* sx = fsm;
        float* sy = fsm + PP;
        float* sz = fsm + 2 * PP;
        uint2* swp = (uint2*)(fsm + 3 * PP);   // double-buffered: 2 x 16

        const int b    = bid;
        const int lane = tid & 31;
        const int wid  = tid >> 5;             // 0..15

        const float* pb = pos + (size_t)b * PP * 3;
        for (int j = tid; j < PP; j += 512) {
            sx[j] = pb[3 * j + 0];
            sy[j] = pb[3 * j + 1];
            sz[j] = pb[3 * j + 2];
        }
        __syncthreads();

        // 8 points/thread: slots tid + 512k, k=0..7, packed in 4 pairs
        ull X[4], Y[4], Z[4];
        float dist[8];
#pragma unroll
        for (int p = 0; p < 4; p++) {
            int j0 = tid + (2 * p) * 512, j1 = tid + (2 * p + 1) * 512;
            PACK2(X[p], sx[j0], sx[j1]);
            PACK2(Y[p], sy[j0], sy[j1]);
            PACK2(Z[p], sz[j0], sz[j1]);
            dist[2 * p] = INFINITY; dist[2 * p + 1] = INFINITY;
        }

        if (tid == 0) g_fps[b * MM] = 0;

        int last = 0;
        for (int i = 1; i < MM; i++) {
            float lx = sx[last], ly = sy[last], lz = sz[last];
            float nlx = -lx, nly = -ly, nlz = -lz;
            ull NLX, NLY, NLZ;
            PACK2(NLX, nlx, nlx); PACK2(NLY, nly, nly); PACK2(NLZ, nlz, nlz);

#pragma unroll
            for (int p = 0; p < 4; p++) {
                // d = ((dx*dx + dy*dy) + dz*dz), no fma -> bitwise == scalar rn
                ull dx, dy, dz, mx, my, mz, t2, dd;
                ADD2(dx, X[p], NLX); ADD2(dy, Y[p], NLY); ADD2(dz, Z[p], NLZ);
                MUL2(mx, dx, dx); MUL2(my, dy, dy); MUL2(mz, dz, dz);
                ADD2(t2, mx, my); ADD2(dd, t2, mz);
                float dlo, dhi;
                UNPACK2(dlo, dhi, dd);
                dist[2 * p]     = fminf(dist[2 * p],     dlo);
                dist[2 * p + 1] = fminf(dist[2 * p + 1], dhi);
            }

            // per-thread argmax, ascending slot index, strict > keeps min idx
            float bv = -1.0f; unsigned bj = 0;
#pragma unroll
            for (int k = 0; k < 8; k++) {
                if (dist[k] > bv) { bv = dist[k]; bj = (unsigned)(tid + k * 512); }
            }

            // warp argmax, first-index tie-break (dist>=0 -> bits order-preserving)
            unsigned vb = __float_as_uint(bv);
            unsigned wm = __reduce_max_sync(0xffffffffu, vb);
            unsigned cj = (vb == wm) ? bj : 0xffffffffu;
            unsigned wj = __reduce_min_sync(0xffffffffu, cj);

            uint2* buf = swp + ((i & 1) << 4);
            if (lane == 0) buf[wid] = make_uint2(wm, wj);
            __syncthreads();
            // all warps redundantly reduce 16 warp results (single barrier/iter:
            // next iter writes the OTHER buffer; barrier of iter i+1 protects reuse)
            uint2 e = (lane < 16) ? buf[lane] : make_uint2(0u, 0xffffffffu);
            unsigned gm  = __reduce_max_sync(0xffffffffu, e.x);
            unsigned cj2 = (e.x == gm) ? e.y : 0xffffffffu;
            unsigned gj  = __reduce_min_sync(0xffffffffu, cj2);
            last = (int)gj;
            if (tid == 0) {
                g_fps[b * MM + i] = last;
                if ((i & 127) == 127) {       // publish 128, 256, ..., 1024
                    __threadfence();
                    atomicExch(&g_prog[b], i + 1);
                }
            }
        }
    } else if (bid < BB + N_MLP_BLOCKS) {
        // ---------------- MLP (+xx) path: 256 rows per block ----------------
        float* sW = fsm;               // 8192 floats (32 KB)
        float* sF = fsm + FIN * FOUT;  // 16384 floats (64 KB)

        const int row0 = (bid - BB) * 256;

        for (int l = tid; l < FIN * FOUT; l += 512) sW[l] = W[l];
        float4* sF4 = (float4*)sF;
        const float4* feat4 = (const float4*)(feat + (size_t)row0 * FIN);
        for (int l = tid; l < 256 * (FIN / 4); l += 512) sF4[l] = feat4[l];
        __syncthreads();

        if (tid < 256) {
            float a0 = 0.f, a1 = 0.f, a2 = 0.f, a3 = 0.f;
#pragma unroll
            for (int d = 0; d < FIN / 4; d++) {
                float4 v = sF4[tid * (FIN / 4) + d];
                a0 += v.x * v.x; a1 += v.y * v.y; a2 += v.z * v.z; a3 += v.w * v.w;
            }
            g_xx[row0 + tid] = (a0 + a1) + (a2 + a3);
        }

        const int col = tid & 127;
        const int grp = tid >> 7;          // 0..3, 64 rows each
        const int rbase = grp * 64;
        const float bc = bias[col];
        float s1 = 0.f, s2 = 0.f;

        for (int r = rbase; r < rbase + 64; r += 2) {
            float a0 = bc, a1 = bc;
#pragma unroll
            for (int d4 = 0; d4 < FIN / 4; d4++) {
                float4 f0 = sF4[r * (FIN / 4) + d4];
                float4 f1 = sF4[(r + 1) * (FIN / 4) + d4];
                float w0 = sW[(d4 * 4 + 0) * FOUT + col];
                float w1 = sW[(d4 * 4 + 1) * FOUT + col];
                float w2 = sW[(d4 * 4 + 2) * FOUT + col];
                float w3 = sW[(d4 * 4 + 3) * FOUT + col];
                a0 += f0.x * w0; a0 += f0.y * w1; a0 += f0.z * w2; a0 += f0.w * w3;
                a1 += f1.x * w0; a1 += f1.y * w1; a1 += f1.z * w2; a1 += f1.w * w3;
            }
            g_h[(size_t)(row0 + r)     * FOUT + col] = a0;
            g_h[(size_t)(row0 + r + 1) * FOUT + col] = a1;
            s1 += a0 + a1;
            s2 += a0 * a0 + a1 * a1;
        }
        const int prow = (bid - BB) * 4 + grp;   // 0..1023
        g_psum[prow * FOUT + col] = s1;
        g_psq [prow * FOUT + col] = s2;

        __syncthreads();                 // all block writes done
        if (tid == 0) {
            __threadfence();
            atomicAdd(&g_mlp_done, 1);
        }
    } else {
        // ---------------- KNN path (R3 body): 512 thr, 4 subs x 1024 ----------------
        char* ksm = (char*)fsm;
        float* sTile = (float*)ksm;                 // 4*32*64 f32 = 32 KB (loop phase)
        ull*   mbuf  = (ull*)ksm;                   // 64*128*8B  = 64 KB (merge phase)
        float* sxx   = (float*)(ksm + 65536);       // 4*32 f32

        const int kb    = bid - (BB + N_MLP_BLOCKS);  // 0..127, chunk-major
        const int chunk = kb >> 4;                    // 0..7
        const int b     = kb & 15;                    // 0..15
        const int sub = tid >> 7;          // 0..3
        const int q   = tid & 127;
        const int m = chunk * 128 + q;

        // spin until dependencies are published
        if (tid == 0) {
            while (atomicAdd(&g_mlp_done, 0) < N_MLP_BLOCKS) __nanosleep(200);
            const int need = chunk * 128 + 128;
            while (atomicAdd(&g_prog[b], 0) < need) __nanosleep(200);
            __threadfence();
        }
        __syncthreads();

        const int qi = g_fps[b * MM + m];
        const float4* qrow = (const float4*)(feat + ((size_t)b * PP + qi) * FIN);
        ull qp[32];
#pragma unroll
        for (int d = 0; d < FIN / 4; d++) {
            float4 f = qrow[d];
            PACK2(qp[2 * d],     f.x, f.y);
            PACK2(qp[2 * d + 1], f.z, f.w);
        }
        const float qq = g_xx[(size_t)b * PP + qi];

        float topv[KK];
        int   topi[KK];
#pragma unroll
        for (int s = 0; s < KK; s++) { topv[s] = INFINITY; topi[s] = 0x7fffffff; }
        float worst = INFINITY;

        const float4* fb4 = (const float4*)(feat + (size_t)b * PP * FIN);
        float4* sT4 = (float4*)sTile;

        for (int p0 = 0; p0 < 1024; p0 += 32) {
            __syncthreads();
            // cooperative tile load: pass i loads sub i's 32 rows
#pragma unroll
            for (int i = 0; i < 4; i++) {
                int row = tid >> 4;          // 0..31
                int c4  = tid & 15;
                int grow = i * 1024 + p0 + row;
                sT4[i * 512 + tid] = fb4[(size_t)grow * (FIN / 4) + c4];
            }
            if (tid < 128) {
                int sx_sub = tid >> 5, r = tid & 31;
                sxx[tid] = g_xx[(size_t)b * PP + sx_sub * 1024 + p0 + r];
            }
            __syncthreads();

#pragma unroll 2
            for (int c = 0; c < 32; c++) {
                const ulonglong2* xr = (const ulonglong2*)(sTile + (size_t)(sub * 32 + c) * FIN);
                ull a01 = 0ull, a23 = 0ull;
#pragma unroll
                for (int d = 0; d < FIN / 4; d++) {
                    ulonglong2 xv = xr[d];
                    FMA2(a01, qp[2 * d],     xv.x);
                    FMA2(a23, qp[2 * d + 1], xv.y);
                }
                float a0, a1, a2, a3;
                UNPACK2(a0, a1, a01);
                UNPACK2(a2, a3, a23);
                float dot = (a0 + a1) + (a2 + a3);
                float d2  = (qq - 2.0f * dot) + sxx[sub * 32 + c];
                if (d2 < worst) {
                    int cand = sub * 1024 + p0 + c;
                    float mv = topv[0]; int mi = topi[0]; int msl = 0;
#pragma unroll
                    for (int s = 1; s < KK; s++) {
                        bool better = (topv[s] > mv) || (topv[s] == mv && topi[s] > mi);
                        if (better) { mv = topv[s]; mi = topi[s]; msl = s; }
                    }
#pragma unroll
                    for (int s = 0; s < KK; s++) {
                        if (s == msl) { topv[s] = d2; topi[s] = cand; }
                    }
                    worst = topv[0];
#pragma unroll
                    for (int s = 1; s < KK; s++) worst = fmaxf(worst, topv[s]);
                }
            }
        }

        // ---- exact merge: key = (monotone(d2) << 32) | idx ----
        __syncthreads();   // tile reads done; reuse smem as mbuf
#pragma unroll
        for (int s = 0; s < KK; s++) {
            unsigned v = __float_as_uint(topv[s]);
            unsigned u = (v & 0x80000000u) ? ~v : (v | 0x80000000u);
            mbuf[(size_t)(sub * KK + s) * 128 + q] = ((ull)u << 32) | (unsigned)topi[s];
        }
        __syncthreads();

        if (sub == 0) {
            int base = (b * MM + m) * KK;
#pragma unroll 1
            for (int k = 0; k < KK; k++) {
                ull best = 0xffffffffffffffffull; int jb = 0;
                for (int j = 0; j < 64; j++) {
                    ull e = mbuf[(size_t)j * 128 + q];
                    if (e < best) { best = e; jb = j; }
                }
                mbuf[(size_t)jb * 128 + q] = 0xffffffffffffffffull;
                g_knn[base + k] = (int)(unsigned)(best & 0xffffffffu);
            }
        }
    }
}

// Deterministic BN stat reduction: one block per column, fixed-order tree.
__global__ void bn_reduce_kernel()
{
    __shared__ float r1[256], r2[256];
    const int col = blockIdx.x;
    const int tid = threadIdx.x;
    float s1 = 0.f, s2 = 0.f;
    for (int i = tid; i < 1024; i += 256) {
        s1 += g_psum[i * FOUT + col];
        s2 += g_psq [i * FOUT + col];
    }
    r1[tid] = s1; r2[tid] = s2;
    __syncthreads();
    for (int off = 128; off > 0; off >>= 1) {
        if (tid < off) { r1[tid] += r1[tid + off]; r2[tid] += r2[tid + off]; }
        __syncthreads();
    }
    if (tid == 0) {
        float mean = r1[0] / (float)NN;
        float var  = r2[0] / (float)NN - mean * mean;
        if (var < 0.f) var = 0.f;
        g_mean[col] = mean;
        g_var [col] = var;
    }
}

// ============================================================
// Gather + fused BN + ReLU + max-pool over K neighbors.
// ============================================================
__global__ void gather_kernel(const float* __restrict__ pos,
                              const float* __restrict__ gamma,
                              const float* __restrict__ beta,
                              float* __restrict__ out,
                              int out_size)
{
    __shared__ int sidx[KK];
    __shared__ int sfps;
    const int q   = blockIdx.x;
    const int b   = q >> 10;
    const int tid = threadIdx.x;

    if (tid < KK) sidx[tid] = g_knn[q * KK + tid];
    if (tid == KK) sfps = g_fps[q];
    __syncthreads();

    const int col = tid;
    float mean = g_mean[col];
    float rstd = rsqrtf(g_var[col] + BN_EPS);
    float ga = gamma[col], be = beta[col];
    const float* hb = g_h + (size_t)b * PP * FOUT;

    float mx = -INFINITY;
#pragma unroll
    for (int k = 0; k < KK; k++) {
        float v = hb[(size_t)sidx[k] * FOUT + col];
        v = (v - mean) * rstd * ga + be;
        v = fmaxf(v, 0.f);
        mx = fmaxf(mx, v);
    }
    out[(size_t)q * FOUT + col] = mx;

    if (out_size >= TOTAL_OUT) {
        if (tid < 3) out[OFF_P + q * 3 + tid] = pos[((size_t)b * PP + sfps) * 3 + tid];
        if (tid == 3) out[OFF_B + q] = (float)b;
    }
}

// ============================================================
extern "C" void kernel_launch(void* const* d_in, const int* in_sizes, int n_in,
                              void* d_out, int out_size)
{
    const float* pos   = (const float*)d_in[0];
    const float* feat  = (const float*)d_in[1];
    // d_in[2] = batch_indices (unused: clouds are sorted & equal-sized)
    const float* W     = (const float*)d_in[3];
    const float* bias  = (const float*)d_in[4];
    const float* gamma = (const float*)d_in[5];
    const float* beta  = (const float*)d_in[6];
    float* out = (float*)d_out;

    // mega smem: max(FPS 48.3KB, MLP 96KB, KNN 66.1KB) = 96 KB
    const int mega_smem = (FIN * FOUT + 256 * FIN) * sizeof(float);   // 98304
    cudaFuncSetAttribute(mega_kernel, cudaFuncAttributeMaxDynamicSharedMemorySize, mega_smem);

    init_kernel<<<1, 32>>>();
    mega_kernel<<<MEGA_BLOCKS, 512, mega_smem>>>(pos, feat, W, bias);
    bn_reduce_kernel<<<FOUT, 256>>>();
    gather_kernel<<<BB * MM, 128>>>(pos, gamma, beta, out, out_size);
}

// round 14
// speedup vs baseline: 1.4272x; 1.0501x over previous
#include <cuda_runtime.h>
#include <cuda_bf16.h>
#include <math.h>

// Problem constants
#define BB   16
#define PP   4096
#define MM   1024
#define KK   16
#define FIN  64
#define FOUT 128
#define NN   (BB * PP)          // 65536
#define BN_EPS 1e-5f

#define OFF_P  (BB * MM * FOUT)            // 2097152
#define OFF_B  (OFF_P + BB * MM * 3)       // 2146304
#define TOTAL_OUT (OFF_B + BB * MM)        // 2162688

#define N_MLP_BLOCKS 256
#define N_KNN_BLOCKS 256                    // 8 chunks x 16 clouds x 2 halves
#define MEGA_BLOCKS  (BB + N_MLP_BLOCKS + N_KNN_BLOCKS)   // 528

// f32x2 packed ops (sm_103a): two independent rn-rounded fp32 ops ->
// bitwise identical to the scalar sequences they replace.
#define PACK2(o, lo, hi)  asm("mov.b64 %0, {%1, %2};" : "=l"(o) : "f"(lo), "f"(hi))
#define UNPACK2(lo, hi, i) asm("mov.b64 {%0, %1}, %2;" : "=f"(lo), "=f"(hi) : "l"(i))
#define FMA2(acc, a, b)   asm("fma.rn.f32x2 %0, %1, %2, %0;" : "+l"(acc) : "l"(a), "l"(b))
#define ADD2(o, a, b)     asm("add.rn.f32x2 %0, %1, %2;" : "=l"(o) : "l"(a), "l"(b))
#define MUL2(o, a, b)     asm("mul.rn.f32x2 %0, %1, %2;" : "=l"(o) : "l"(a), "l"(b))

typedef unsigned long long ull;

// -------- scratch (static device globals; no allocation allowed) --------
__device__ int   g_fps[BB * MM];
__device__ ull   g_keys[(size_t)BB * MM * 32];  // per query: 2 halves x 16 sorted keys
__device__ float g_h[(size_t)NN * FOUT];        // 33.5 MB pre-BN activations
__device__ float g_psum[1024 * FOUT];           // 1024 x 128 partial sums (64 rows each)
__device__ float g_psq [1024 * FOUT];
__device__ float g_mean[FOUT];
__device__ float g_var [FOUT];
__device__ float g_xx[NN];                      // per-point sum(x*x) in feature space
// cross-block progress (reset by init kernel every call)
__device__ int   g_prog[BB];                    // fps indices published per cloud
__device__ int   g_mlp_done;                    // completed mlp blocks

__global__ void init_kernel()
{
    int t = threadIdx.x;
    if (t < BB) g_prog[t] = 0;
    if (t == 31) g_mlp_done = 0;
}

// ============================================================
// Mega kernel, 512 threads/block:
//   blocks [0,16)    : FPS (one cloud each, publishes progress/128)
//   blocks [16,272)  : MLP (+xx) on 256 rows each, signals done
//   blocks [272,528) : KNN half-chunk (128 queries x 2048 candidates),
//                      spins on progress, emits sorted top-16 keys.
// ============================================================
__global__ void __launch_bounds__(512) mega_kernel(
    const float* __restrict__ pos,
    const float* __restrict__ feat,
    const float* __restrict__ W,
    const float* __restrict__ bias)
{
    extern __shared__ float fsm[];
    const int tid = threadIdx.x;
    const int bid = blockIdx.x;

    if (bid < BB) {
        // ---------------- FPS path: 512 thr, 8 pts/thread (R9-proven) ----------------
        float* sx = fsm;
        float* sy = fsm + PP;
        float* sz = fsm + 2 * PP;
        uint2* swp = (uint2*)(fsm + 3 * PP);   // double-buffered: 2 x 16

        const int b    = bid;
        const int lane = tid & 31;
        const int wid  = tid >> 5;             // 0..15

        const float* pb = pos + (size_t)b * PP * 3;
        for (int j = tid; j < PP; j += 512) {
            sx[j] = pb[3 * j + 0];
            sy[j] = pb[3 * j + 1];
            sz[j] = pb[3 * j + 2];
        }
        __syncthreads();

        ull X[4], Y[4], Z[4];
        float dist[8];
#pragma unroll
        for (int p = 0; p < 4; p++) {
            int j0 = tid + (2 * p) * 512, j1 = tid + (2 * p + 1) * 512;
            PACK2(X[p], sx[j0], sx[j1]);
            PACK2(Y[p], sy[j0], sy[j1]);
            PACK2(Z[p], sz[j0], sz[j1]);
            dist[2 * p] = INFINITY; dist[2 * p + 1] = INFINITY;
        }

        if (tid == 0) g_fps[b * MM] = 0;

        int last = 0;
        for (int i = 1; i < MM; i++) {
            float lx = sx[last], ly = sy[last], lz = sz[last];
            float nlx = -lx, nly = -ly, nlz = -lz;
            ull NLX, NLY, NLZ;
            PACK2(NLX, nlx, nlx); PACK2(NLY, nly, nly); PACK2(NLZ, nlz, nlz);

#pragma unroll
            for (int p = 0; p < 4; p++) {
                // d = ((dx*dx + dy*dy) + dz*dz), no fma -> bitwise == scalar rn
                ull dx, dy, dz, mx, my, mz, t2, dd;
                ADD2(dx, X[p], NLX); ADD2(dy, Y[p], NLY); ADD2(dz, Z[p], NLZ);
                MUL2(mx, dx, dx); MUL2(my, dy, dy); MUL2(mz, dz, dz);
                ADD2(t2, mx, my); ADD2(dd, t2, mz);
                float dlo, dhi;
                UNPACK2(dlo, dhi, dd);
                dist[2 * p]     = fminf(dist[2 * p],     dlo);
                dist[2 * p + 1] = fminf(dist[2 * p + 1], dhi);
            }

            // per-thread argmax, ascending slot index, strict > keeps min idx
            float bv = -1.0f; unsigned bj = 0;
#pragma unroll
            for (int k = 0; k < 8; k++) {
                if (dist[k] > bv) { bv = dist[k]; bj = (unsigned)(tid + k * 512); }
            }

            // warp argmax, first-index tie-break (dist>=0 -> bits order-preserving)
            unsigned vb = __float_as_uint(bv);
            unsigned wm = __reduce_max_sync(0xffffffffu, vb);
            unsigned cj = (vb == wm) ? bj : 0xffffffffu;
            unsigned wj = __reduce_min_sync(0xffffffffu, cj);

            uint2* buf = swp + ((i & 1) << 4);
            if (lane == 0) buf[wid] = make_uint2(wm, wj);
            __syncthreads();
            // all warps redundantly reduce 16 warp results (single barrier/iter)
            uint2 e = (lane < 16) ? buf[lane] : make_uint2(0u, 0xffffffffu);
            unsigned gm  = __reduce_max_sync(0xffffffffu, e.x);
            unsigned cj2 = (e.x == gm) ? e.y : 0xffffffffu;
            unsigned gj  = __reduce_min_sync(0xffffffffu, cj2);
            last = (int)gj;
            if (tid == 0) {
                g_fps[b * MM + i] = last;
                if ((i & 127) == 127) {       // publish 128, 256, ..., 1024
                    __threadfence();
                    atomicExch(&g_prog[b], i + 1);
                }
            }
        }
    } else if (bid < BB + N_MLP_BLOCKS) {
        // ---------------- MLP (+xx) path: 256 rows per block (R9-proven) ----------------
        float* sW = fsm;               // 8192 floats (32 KB)
        float* sF = fsm + FIN * FOUT;  // 16384 floats (64 KB)

        const int row0 = (bid - BB) * 256;

        for (int l = tid; l < FIN * FOUT; l += 512) sW[l] = W[l];
        float4* sF4 = (float4*)sF;
        const float4* feat4 = (const float4*)(feat + (size_t)row0 * FIN);
        for (int l = tid; l < 256 * (FIN / 4); l += 512) sF4[l] = feat4[l];
        __syncthreads();

        if (tid < 256) {
            float a0 = 0.f, a1 = 0.f, a2 = 0.f, a3 = 0.f;
#pragma unroll
            for (int d = 0; d < FIN / 4; d++) {
                float4 v = sF4[tid * (FIN / 4) + d];
                a0 += v.x * v.x; a1 += v.y * v.y; a2 += v.z * v.z; a3 += v.w * v.w;
            }
            g_xx[row0 + tid] = (a0 + a1) + (a2 + a3);
        }

        const int col = tid & 127;
        const int grp = tid >> 7;          // 0..3, 64 rows each
        const int rbase = grp * 64;
        const float bc = bias[col];
        float s1 = 0.f, s2 = 0.f;

        for (int r = rbase; r < rbase + 64; r += 2) {
            float a0 = bc, a1 = bc;
#pragma unroll
            for (int d4 = 0; d4 < FIN / 4; d4++) {
                float4 f0 = sF4[r * (FIN / 4) + d4];
                float4 f1 = sF4[(r + 1) * (FIN / 4) + d4];
                float w0 = sW[(d4 * 4 + 0) * FOUT + col];
                float w1 = sW[(d4 * 4 + 1) * FOUT + col];
                float w2 = sW[(d4 * 4 + 2) * FOUT + col];
                float w3 = sW[(d4 * 4 + 3) * FOUT + col];
                a0 += f0.x * w0; a0 += f0.y * w1; a0 += f0.z * w2; a0 += f0.w * w3;
                a1 += f1.x * w0; a1 += f1.y * w1; a1 += f1.z * w2; a1 += f1.w * w3;
            }
            g_h[(size_t)(row0 + r)     * FOUT + col] = a0;
            g_h[(size_t)(row0 + r + 1) * FOUT + col] = a1;
            s1 += a0 + a1;
            s2 += a0 * a0 + a1 * a1;
        }
        const int prow = (bid - BB) * 4 + grp;   // 0..1023
        g_psum[prow * FOUT + col] = s1;
        g_psq [prow * FOUT + col] = s2;

        __syncthreads();                 // all block writes done
        if (tid == 0) {
            __threadfence();
            atomicAdd(&g_mlp_done, 1);
        }
    } else {
        // ---------------- KNN half-chunk: 512 thr, 4 subs x 512 candidates ----------------
        char* ksm = (char*)fsm;
        float* sTile = (float*)ksm;                 // 4*32*64 f32 = 32 KB (loop phase)
        ull*   mbuf  = (ull*)ksm;                   // 64*128*8B  = 64 KB (merge phase)
        float* sxx   = (float*)(ksm + 65536);       // 128 f32

        const int kb    = bid - (BB + N_MLP_BLOCKS);  // 0..255, chunk-major
        const int chunk = kb >> 5;                    // 0..7
        const int rem   = kb & 31;
        const int b     = rem >> 1;                   // 0..15
        const int h     = rem & 1;                    // candidate half
        const int cbase = h * 2048;
        const int sub = tid >> 7;          // 0..3
        const int q   = tid & 127;
        const int m = chunk * 128 + q;

        // spin until dependencies are published
        if (tid == 0) {
            while (atomicAdd(&g_mlp_done, 0) < N_MLP_BLOCKS) __nanosleep(200);
            const int need = chunk * 128 + 128;
            while (atomicAdd(&g_prog[b], 0) < need) __nanosleep(200);
            __threadfence();
        }
        __syncthreads();

        const int qi = g_fps[b * MM + m];
        const float4* qrow = (const float4*)(feat + ((size_t)b * PP + qi) * FIN);
        ull qp[32];
#pragma unroll
        for (int d = 0; d < FIN / 4; d++) {
            float4 f = qrow[d];
            PACK2(qp[2 * d],     f.x, f.y);
            PACK2(qp[2 * d + 1], f.z, f.w);
        }
        const float qq = g_xx[(size_t)b * PP + qi];

        float topv[KK];
        int   topi[KK];
#pragma unroll
        for (int s = 0; s < KK; s++) { topv[s] = INFINITY; topi[s] = 0x7fffffff; }
        float worst = INFINITY;

        const float4* fb4 = (const float4*)(feat + (size_t)b * PP * FIN);
        float4* sT4 = (float4*)sTile;

        for (int p0 = 0; p0 < 512; p0 += 32) {
            __syncthreads();
            // cooperative tile load: pass i loads sub i's 32 rows
#pragma unroll
            for (int i = 0; i < 4; i++) {
                int row = tid >> 4;          // 0..31
                int c4  = tid & 15;
                int grow = cbase + i * 512 + p0 + row;
                sT4[i * 512 + tid] = fb4[(size_t)grow * (FIN / 4) + c4];
            }
            if (tid < 128) {
                int ss = tid >> 5, r = tid & 31;
                sxx[tid] = g_xx[(size_t)b * PP + cbase + ss * 512 + p0 + r];
            }
            __syncthreads();

#pragma unroll 2
            for (int c = 0; c < 32; c++) {
                const ulonglong2* xr = (const ulonglong2*)(sTile + (size_t)(sub * 32 + c) * FIN);
                ull a01 = 0ull, a23 = 0ull;
#pragma unroll
                for (int d = 0; d < FIN / 4; d++) {
                    ulonglong2 xv = xr[d];
                    FMA2(a01, qp[2 * d],     xv.x);
                    FMA2(a23, qp[2 * d + 1], xv.y);
                }
                float a0, a1, a2, a3;
                UNPACK2(a0, a1, a01);
                UNPACK2(a2, a3, a23);
                float dot = (a0 + a1) + (a2 + a3);
                float d2  = (qq - 2.0f * dot) + sxx[sub * 32 + c];
                if (d2 < worst) {
                    int cand = cbase + sub * 512 + p0 + c;
                    float mv = topv[0]; int mi = topi[0]; int msl = 0;
#pragma unroll
                    for (int s = 1; s < KK; s++) {
                        bool better = (topv[s] > mv) || (topv[s] == mv && topi[s] > mi);
                        if (better) { mv = topv[s]; mi = topi[s]; msl = s; }
                    }
#pragma unroll
                    for (int s = 0; s < KK; s++) {
                        if (s == msl) { topv[s] = d2; topi[s] = cand; }
                    }
                    worst = topv[0];
#pragma unroll
                    for (int s = 1; s < KK; s++) worst = fmaxf(worst, topv[s]);
                }
            }
        }

        // ---- exact merge across 4 subs: key = (monotone(d2) << 32) | idx ----
        __syncthreads();   // tile reads done; reuse smem as mbuf
#pragma unroll
        for (int s = 0; s < KK; s++) {
            unsigned v = __float_as_uint(topv[s]);
            unsigned u = (v & 0x80000000u) ? ~v : (v | 0x80000000u);
            mbuf[(size_t)(sub * KK + s) * 128 + q] = ((ull)u << 32) | (unsigned)topi[s];
        }
        __syncthreads();

        if (sub == 0) {
            size_t kbase = (size_t)(b * MM + m) * 32 + h * 16;
#pragma unroll 1
            for (int k = 0; k < KK; k++) {       // emits ascending key order
                ull best = 0xffffffffffffffffull; int jb = 0;
                for (int j = 0; j < 64; j++) {
                    ull e = mbuf[(size_t)j * 128 + q];
                    if (e < best) { best = e; jb = j; }
                }
                mbuf[(size_t)jb * 128 + q] = 0xffffffffffffffffull;
                g_keys[kbase + k] = best;
            }
        }
    }
}

// Deterministic BN stat reduction: one block per column, fixed-order tree.
__global__ void bn_reduce_kernel()
{
    __shared__ float r1[256], r2[256];
    const int col = blockIdx.x;
    const int tid = threadIdx.x;
    float s1 = 0.f, s2 = 0.f;
    for (int i = tid; i < 1024; i += 256) {
        s1 += g_psum[i * FOUT + col];
        s2 += g_psq [i * FOUT + col];
    }
    r1[tid] = s1; r2[tid] = s2;
    __syncthreads();
    for (int off = 128; off > 0; off >>= 1) {
        if (tid < off) { r1[tid] += r1[tid + off]; r2[tid] += r2[tid + off]; }
        __syncthreads();
    }
    if (tid == 0) {
        float mean = r1[0] / (float)NN;
        float var  = r2[0] / (float)NN - mean * mean;
        if (var < 0.f) var = 0.f;
        g_mean[col] = mean;
        g_var [col] = var;
    }
}

// ============================================================
// Gather: exact 2-pointer merge of the two sorted half key-lists,
// then fused BN + ReLU + max-pool over the K neighbors.
// ============================================================
__global__ void gather_kernel(const float* __restrict__ pos,
                              const float* __restrict__ gamma,
                              const float* __restrict__ beta,
                              float* __restrict__ out,
                              int out_size)
{
    __shared__ ull skey[32];
    __shared__ int sidx[KK];
    __shared__ int sfps;
    const int q   = blockIdx.x;
    const int b   = q >> 10;
    const int tid = threadIdx.x;

    if (tid < 32) skey[tid] = g_keys[(size_t)q * 32 + tid];
    if (tid == 32) sfps = g_fps[q];
    __syncthreads();

    if (tid == 0) {
        ull c0 = skey[0], c1 = skey[16];
        int h0 = 0, h1 = 0;
#pragma unroll
        for (int k = 0; k < KK; k++) {
            bool take0 = (c0 < c1);
            ull w = take0 ? c0 : c1;
            sidx[k] = (int)(unsigned)(w & 0xffffffffu);
            if (take0) {
                h0++;
                c0 = (h0 < KK) ? skey[h0] : 0xffffffffffffffffull;
            } else {
                h1++;
                c1 = (h1 < KK) ? skey[KK + h1] : 0xffffffffffffffffull;
            }
        }
    }
    __syncthreads();

    const int col = tid;
    float mean = g_mean[col];
    float rstd = rsqrtf(g_var[col] + BN_EPS);
    float ga = gamma[col], be = beta[col];
    const float* hb = g_h + (size_t)b * PP * FOUT;

    float mx = -INFINITY;
#pragma unroll
    for (int k = 0; k < KK; k++) {
        float v = hb[(size_t)sidx[k] * FOUT + col];
        v = (v - mean) * rstd * ga + be;
        v = fmaxf(v, 0.f);
        mx = fmaxf(mx, v);
    }
    out[(size_t)q * FOUT + col] = mx;

    if (out_size >= TOTAL_OUT) {
        if (tid < 3) out[OFF_P + q * 3 + tid] = pos[((size_t)b * PP + sfps) * 3 + tid];
        if (tid == 3) out[OFF_B + q] = (float)b;
    }
}

// ============================================================
extern "C" void kernel_launch(void* const* d_in, const int* in_sizes, int n_in,
                              void* d_out, int out_size)
{
    const float* pos   = (const float*)d_in[0];
    const float* feat  = (const float*)d_in[1];
    // d_in[2] = batch_indices (unused: clouds are sorted & equal-sized)
    const float* W     = (const float*)d_in[3];
    const float* bias  = (const float*)d_in[4];
    const float* gamma = (const float*)d_in[5];
    const float* beta  = (const float*)d_in[6];
    float* out = (float*)d_out;

    // mega smem: max(FPS 48.3KB, MLP 96KB, KNN 64.5KB) = 96 KB
    const int mega_smem = (FIN * FOUT + 256 * FIN) * sizeof(float);   // 98304
    cudaFuncSetAttribute(mega_kernel, cudaFuncAttributeMaxDynamicSharedMemorySize, mega_smem);

    init_kernel<<<1, 32>>>();
    mega_kernel<<<MEGA_BLOCKS, 512, mega_smem>>>(pos, feat, W, bias);
    bn_reduce_kernel<<<FOUT, 256>>>();
    gather_kernel<<<BB * MM, 128>>>(pos, gamma, beta, out, out_size);
}